// round 3
// baseline (speedup 1.0000x reference)
#include <cuda_runtime.h>

// SwinStyleAttention fused kernel, fp32, one CTA per 8x8 window.
// B=8, C=128, H=W=256, WS=8, SS=4, HEADS=4, DH=32, INNER=128, L=64.

#define CCH   128
#define INNER 128
#define L64   64
#define HDIM  256
#define NWIN  8192     // 8 * 32 * 32
#define ATT_SCALE 0.17677669529663687f  // 32^-0.5

// shared memory layout (floats)
#define XS_SZ  (128*64)    // sm_x  [k][t]  (A for qkv; reused as ot[hd][t] for proj)
#define WS_SZ  (128*64)    // sm_w  [k][j]  weight tile
#define Q_SZ   (64*128)    // sm_q  [t][hd]
#define KT_STR 68
#define KT_SZ  (128*KT_STR) // sm_kt [hd][m], padded stride (16B-aligned rows)
#define V_STR  132
#define V_SZ   (64*V_STR)   // sm_v  [m][hd], padded stride
#define S_SZ   (64*64)      // sm_s  scores [t][m]
#define SMEM_FLOATS (XS_SZ + WS_SZ + Q_SZ + KT_SZ + V_SZ + S_SZ)
#define SMEM_BYTES  (SMEM_FLOATS * 4)

__global__ __launch_bounds__(256, 1)
void swin_fused_kernel(const float* __restrict__ x,
                       const float* __restrict__ w_qkv,
                       const float* __restrict__ w_proj,
                       const float* __restrict__ b_proj,
                       float* __restrict__ out)
{
    extern __shared__ float sm[];
    float* sm_x  = sm;
    float* sm_w  = sm_x + XS_SZ;
    float* sm_q  = sm_w + WS_SZ;
    float* sm_kt = sm_q + Q_SZ;
    float* sm_v  = sm_kt + KT_SZ;
    float* sm_s  = sm_v + V_SZ;

    const int tid = threadIdx.x;
    const int win = blockIdx.x;
    const int b   = win >> 10;          // 1024 windows per batch (32x32)
    const int wh  = (win >> 5) & 31;
    const int ww  = win & 31;

    // shifted coords: xh[r][c] = x[(r+SS)%H][(c+SS)%W]; same +SS map for output
    const int row0 = wh * 8 + 4;
    const int col0 = ww * 8 + 4;

    // ---- load window x into sm_x[k][t] (k = channel, t = token) ----
    #pragma unroll
    for (int it = 0; it < 32; ++it) {
        int idx = it * 256 + tid;      // idx = ch*64 + t
        int ch  = idx >> 6;
        int t   = idx & 63;
        int sr  = (row0 + (t >> 3)) & 255;
        int sc  = (col0 + (t & 7)) & 255;
        sm_x[idx] = x[(((b * 128 + ch) << 8) + sr) * 256 + sc];
    }

    const int ty = tid >> 4;           // 0..15 (token tile)
    const int tx = tid & 15;           // 0..15 (j tile)

    // ================= QKV GEMM: [64x128] @ [128x384] ==================
    for (int jt = 0; jt < 6; ++jt) {
        __syncthreads();               // sm_w reuse barrier (also covers x load on jt=0)
        #pragma unroll
        for (int it = 0; it < 32; ++it) {
            int idx = it * 256 + tid;  // k*64 + jj
            int k  = idx >> 6;
            int jj = idx & 63;
            sm_w[idx] = w_qkv[k * 384 + jt * 64 + jj];
        }
        __syncthreads();

        float acc[4][4] = {};
        #pragma unroll 8
        for (int k = 0; k < 128; ++k) {
            float4 a  = *(const float4*)&sm_x[k * 64 + ty * 4];
            float4 bb = *(const float4*)&sm_w[k * 64 + tx * 4];
            acc[0][0] += a.x * bb.x; acc[0][1] += a.x * bb.y; acc[0][2] += a.x * bb.z; acc[0][3] += a.x * bb.w;
            acc[1][0] += a.y * bb.x; acc[1][1] += a.y * bb.y; acc[1][2] += a.y * bb.z; acc[1][3] += a.y * bb.w;
            acc[2][0] += a.z * bb.x; acc[2][1] += a.z * bb.y; acc[2][2] += a.z * bb.z; acc[2][3] += a.z * bb.w;
            acc[3][0] += a.w * bb.x; acc[3][1] += a.w * bb.y; acc[3][2] += a.w * bb.z; acc[3][3] += a.w * bb.w;
        }

        int jbase = jt * 64 + tx * 4;
        int tbase = ty * 4;
        if (jt < 2) {                  // Q: [t][hd]
            #pragma unroll
            for (int ti = 0; ti < 4; ++ti)
                #pragma unroll
                for (int ji = 0; ji < 4; ++ji)
                    sm_q[(tbase + ti) * 128 + jbase + ji] = acc[ti][ji];
        } else if (jt < 4) {           // K transposed: [hd][m]
            #pragma unroll
            for (int ti = 0; ti < 4; ++ti)
                #pragma unroll
                for (int ji = 0; ji < 4; ++ji)
                    sm_kt[(jbase - 128 + ji) * KT_STR + tbase + ti] = acc[ti][ji];
        } else {                       // V: [m][hd]
            #pragma unroll
            for (int ti = 0; ti < 4; ++ti)
                #pragma unroll
                for (int ji = 0; ji < 4; ++ji)
                    sm_v[(tbase + ti) * V_STR + jbase - 256 + ji] = acc[ti][ji];
        }
    }
    __syncthreads();

    // ================= Attention per head ==================
    const int lane = tid & 31;
    const int warp = tid >> 5;

    for (int h = 0; h < 4; ++h) {
        const int hd0 = h * 32;

        // ---- scores S = Q Kt * SCALE : 64x64, K-dim 32 ----
        #pragma unroll
        for (int i = 0; i < 4; ++i) {
            int item = i * 256 + tid;  // 1024 items: t*16 + mg
            int t  = item >> 4;
            int m0 = (item & 15) * 4;
            float4 accv = make_float4(0.f, 0.f, 0.f, 0.f);
            #pragma unroll 8
            for (int d = 0; d < 32; ++d) {
                float  qv = sm_q[t * 128 + hd0 + d];
                float4 kv = *(const float4*)&sm_kt[(hd0 + d) * KT_STR + m0];
                accv.x += qv * kv.x; accv.y += qv * kv.y;
                accv.z += qv * kv.z; accv.w += qv * kv.w;
            }
            sm_s[t * 64 + m0 + 0] = accv.x * ATT_SCALE;
            sm_s[t * 64 + m0 + 1] = accv.y * ATT_SCALE;
            sm_s[t * 64 + m0 + 2] = accv.z * ATT_SCALE;
            sm_s[t * 64 + m0 + 3] = accv.w * ATT_SCALE;
        }
        __syncthreads();

        // ---- softmax over rows of 64 (8 warps x 8 rows) ----
        #pragma unroll
        for (int rr = 0; rr < 8; ++rr) {
            int r = warp * 8 + rr;
            float v0 = sm_s[r * 64 + lane];
            float v1 = sm_s[r * 64 + lane + 32];
            float mx = fmaxf(v0, v1);
            #pragma unroll
            for (int off = 16; off > 0; off >>= 1)
                mx = fmaxf(mx, __shfl_xor_sync(0xffffffffu, mx, off));
            float e0 = __expf(v0 - mx);
            float e1 = __expf(v1 - mx);
            float s = e0 + e1;
            #pragma unroll
            for (int off = 16; off > 0; off >>= 1)
                s += __shfl_xor_sync(0xffffffffu, s, off);
            float inv = 1.0f / s;
            sm_s[r * 64 + lane]      = e0 * inv;
            sm_s[r * 64 + lane + 32] = e1 * inv;
        }
        __syncthreads();

        // ---- O = P V : 64x32, K-dim 64; write transposed into sm_x as ot[hd][t] ----
        #pragma unroll
        for (int i = 0; i < 2; ++i) {
            int item = i * 256 + tid;  // 512 items: t*8 + dg
            int t  = item >> 3;
            int d0 = (item & 7) * 4;
            float4 accv = make_float4(0.f, 0.f, 0.f, 0.f);
            #pragma unroll 8
            for (int m = 0; m < 64; ++m) {
                float  p  = sm_s[t * 64 + m];
                float4 vv = *(const float4*)&sm_v[m * V_STR + hd0 + d0];
                accv.x += p * vv.x; accv.y += p * vv.y;
                accv.z += p * vv.z; accv.w += p * vv.w;
            }
            sm_x[(hd0 + d0 + 0) * 64 + t] = accv.x;
            sm_x[(hd0 + d0 + 1) * 64 + t] = accv.y;
            sm_x[(hd0 + d0 + 2) * 64 + t] = accv.z;
            sm_x[(hd0 + d0 + 3) * 64 + t] = accv.w;
        }
        __syncthreads();
    }

    // ================= Proj GEMM: ot[64x128] @ w_proj[128x128] + b ==================
    for (int jt = 0; jt < 2; ++jt) {
        __syncthreads();
        #pragma unroll
        for (int it = 0; it < 32; ++it) {
            int idx = it * 256 + tid;
            int k  = idx >> 6;
            int jj = idx & 63;
            sm_w[idx] = w_proj[k * 128 + jt * 64 + jj];
        }
        __syncthreads();

        float acc[4][4] = {};
        #pragma unroll 8
        for (int k = 0; k < 128; ++k) {
            float4 a  = *(const float4*)&sm_x[k * 64 + ty * 4];
            float4 bb = *(const float4*)&sm_w[k * 64 + tx * 4];
            acc[0][0] += a.x * bb.x; acc[0][1] += a.x * bb.y; acc[0][2] += a.x * bb.z; acc[0][3] += a.x * bb.w;
            acc[1][0] += a.y * bb.x; acc[1][1] += a.y * bb.y; acc[1][2] += a.y * bb.z; acc[1][3] += a.y * bb.w;
            acc[2][0] += a.z * bb.x; acc[2][1] += a.z * bb.y; acc[2][2] += a.z * bb.z; acc[2][3] += a.z * bb.w;
            acc[3][0] += a.w * bb.x; acc[3][1] += a.w * bb.y; acc[3][2] += a.w * bb.z; acc[3][3] += a.w * bb.w;
        }

        float bp[4];
        #pragma unroll
        for (int ji = 0; ji < 4; ++ji)
            bp[ji] = __ldg(&b_proj[jt * 64 + tx * 4 + ji]);

        #pragma unroll
        for (int ti = 0; ti < 4; ++ti) {
            int t  = ty * 4 + ti;
            int gr = (row0 + (t >> 3)) & 255;
            int gc = (col0 + (t & 7)) & 255;
            #pragma unroll
            for (int ji = 0; ji < 4; ++ji) {
                int c = jt * 64 + tx * 4 + ji;
                out[(((b * 128 + c) << 8) + gr) * 256 + gc] = acc[ti][ji] + bp[ji];
            }
        }
    }
}

extern "C" void kernel_launch(void* const* d_in, const int* in_sizes, int n_in,
                              void* d_out, int out_size)
{
    const float* x      = (const float*)d_in[0];
    const float* w_qkv  = (const float*)d_in[1];
    const float* w_proj = (const float*)d_in[2];
    const float* b_proj = (const float*)d_in[3];
    float* out = (float*)d_out;

    cudaFuncSetAttribute(swin_fused_kernel,
                         cudaFuncAttributeMaxDynamicSharedMemorySize, SMEM_BYTES);

    swin_fused_kernel<<<NWIN, 256, SMEM_BYTES>>>(x, w_qkv, w_proj, b_proj, out);
}

// round 9
// speedup vs baseline: 1.5114x; 1.5114x over previous
#include <cuda_runtime.h>

// SwinStyleAttention fused kernel, fp32 + packed f32x2 FMA, one CTA per 8x8 window.
// B=8, C=128, H=W=256, WS=8, SS=4, HEADS=4, DH=32, INNER=128, L=64.

#define NWIN  8192
#define ATT_SCALE 0.17677669529663687f  // 32^-0.5

// shared memory layout (floats)
#define XS_SZ  (128*64)     // sm_x  [k][t]   (A for qkv; reused as O^T[d][t] for proj)
#define WW_SZ  (128*128)    // sm_w  [k][j]   weight tile; overlaid by S^T (4 heads x 64x64)
#define QT_SZ  (128*64)     // sm_qt [hd][t]
#define KT_SZ  (128*64)     // sm_kt [hd][t]
#define V_STR  128
#define V_SZ   (64*V_STR)   // sm_v  [m][hd]
#define SMEM_FLOATS (XS_SZ + WW_SZ + QT_SZ + KT_SZ + V_SZ)
#define SMEM_BYTES  (SMEM_FLOATS * 4)   // 192 KB

typedef unsigned long long u64;

#define FMA2(acc, aa, bb) \
    asm("fma.rn.f32x2 %0, %1, %2, %0;" : "+l"(acc) : "l"(aa), "l"(bb))
#define MUL2(dst, aa, bb) \
    asm("mul.rn.f32x2 %0, %1, %2;" : "=l"(dst) : "l"(aa), "l"(bb))
#define BCAST(dst, f) \
    asm("mov.b64 %0, {%1, %1};" : "=l"(dst) : "f"(f))

union F2U { u64 u; float f[2]; };

__global__ __launch_bounds__(256, 1)
void swin_fused_kernel(const float* __restrict__ x,
                       const float* __restrict__ w_qkv,
                       const float* __restrict__ w_proj,
                       const float* __restrict__ b_proj,
                       float* __restrict__ out)
{
    extern __shared__ float sm[];
    float* sm_x  = sm;
    float* sm_w  = sm_x + XS_SZ;     // also S^T region: head h at sm_w + h*4096, [m][t] stride 64
    float* sm_qt = sm_w + WW_SZ;
    float* sm_kt = sm_qt + QT_SZ;
    float* sm_v  = sm_kt + KT_SZ;

    const int tid = threadIdx.x;
    const int win = blockIdx.x;
    const int b   = win >> 10;
    const int wh  = (win >> 5) & 31;
    const int ww  = win & 31;

    const int row0 = wh * 8 + 4;     // cyclic shift folded into gather/scatter
    const int col0 = ww * 8 + 4;

    // ---- load window x into sm_x[k][t] ----
    #pragma unroll
    for (int it = 0; it < 32; ++it) {
        int idx = it * 256 + tid;     // ch*64 + t
        int ch  = idx >> 6;
        int t   = idx & 63;
        int sr  = (row0 + (t >> 3)) & 255;
        int sc  = (col0 + (t & 7)) & 255;
        sm_x[idx] = x[(((b * 128 + ch) << 8) + sr) * 256 + sc];
    }

    // ================= QKV GEMM: [64t x 128k] @ [128k x 384] in 3 j-tiles of 128 =============
    // microtile: 8 tokens x 4 cols per thread; acc packed in f32x2 pairs along t.
    {
        const int ty = tid >> 5;          // 0..7 -> t0 = ty*8
        const int tx = tid & 31;          // 0..31 -> j0 = tx*4
        const int t0 = ty * 8;
        const int j0 = tx * 4;

        for (int jt = 0; jt < 3; ++jt) {
            __syncthreads();
            // load weight tile [128k][128j] with float4
            #pragma unroll
            for (int it = 0; it < 16; ++it) {
                int idx = it * 256 + tid;         // float4 index: k*32 + jq
                int k  = idx >> 5;
                int jq = idx & 31;
                *(float4*)&sm_w[k * 128 + jq * 4] =
                    *(const float4*)&w_qkv[k * 384 + jt * 128 + jq * 4];
            }
            __syncthreads();

            u64 acc[4][4];
            #pragma unroll
            for (int p = 0; p < 4; ++p)
                #pragma unroll
                for (int j = 0; j < 4; ++j) acc[p][j] = 0ull;

            #pragma unroll 4
            for (int k = 0; k < 128; ++k) {
                ulonglong2 A0 = *(const ulonglong2*)&sm_x[k * 64 + t0];
                ulonglong2 A1 = *(const ulonglong2*)&sm_x[k * 64 + t0 + 4];
                float4 bv = *(const float4*)&sm_w[k * 128 + j0];
                u64 bb[4];
                BCAST(bb[0], bv.x); BCAST(bb[1], bv.y);
                BCAST(bb[2], bv.z); BCAST(bb[3], bv.w);
                u64 ap[4] = {A0.x, A0.y, A1.x, A1.y};
                #pragma unroll
                for (int p = 0; p < 4; ++p)
                    #pragma unroll
                    for (int j = 0; j < 4; ++j)
                        FMA2(acc[p][j], ap[p], bb[j]);
            }

            if (jt == 0) {            // Q^T[hd][t]
                #pragma unroll
                for (int p = 0; p < 4; ++p)
                    #pragma unroll
                    for (int j = 0; j < 4; ++j)
                        *(u64*)&sm_qt[(j0 + j) * 64 + t0 + 2 * p] = acc[p][j];
            } else if (jt == 1) {     // K^T[hd][t]
                #pragma unroll
                for (int p = 0; p < 4; ++p)
                    #pragma unroll
                    for (int j = 0; j < 4; ++j)
                        *(u64*)&sm_kt[(j0 + j) * 64 + t0 + 2 * p] = acc[p][j];
            } else {                  // V[m][hd]  (scatter unpack)
                #pragma unroll
                for (int p = 0; p < 4; ++p)
                    #pragma unroll
                    for (int j = 0; j < 4; ++j) {
                        F2U cv; cv.u = acc[p][j];
                        sm_v[(t0 + 2 * p)     * V_STR + j0 + j] = cv.f[0];
                        sm_v[(t0 + 2 * p + 1) * V_STR + j0 + j] = cv.f[1];
                    }
            }
        }
    }
    __syncthreads();   // qt/kt/v ready; sm_w free for S^T

    // ================= Scores: S^T[h][m][t] = (Q K^T)^T * SCALE, all heads =================
    // microtile: 4t x 4m per thread per head; K-dim 32.
    {
        const int t0 = (tid >> 4) * 4;    // 16 groups x 4 = 64 tokens
        const int m0 = (tid & 15) * 4;
        u64 s2; BCAST(s2, ATT_SCALE);

        #pragma unroll
        for (int h = 0; h < 4; ++h) {
            const int hd0 = h * 32;
            float* st = sm_w + h * 4096;

            u64 acc[2][4];
            #pragma unroll
            for (int p = 0; p < 2; ++p)
                #pragma unroll
                for (int j = 0; j < 4; ++j) acc[p][j] = 0ull;

            #pragma unroll 4
            for (int d = 0; d < 32; ++d) {
                ulonglong2 qa = *(const ulonglong2*)&sm_qt[(hd0 + d) * 64 + t0];
                float4 kv = *(const float4*)&sm_kt[(hd0 + d) * 64 + m0];
                u64 bb[4];
                BCAST(bb[0], kv.x); BCAST(bb[1], kv.y);
                BCAST(bb[2], kv.z); BCAST(bb[3], kv.w);
                u64 ap[2] = {qa.x, qa.y};
                #pragma unroll
                for (int p = 0; p < 2; ++p)
                    #pragma unroll
                    for (int j = 0; j < 4; ++j)
                        FMA2(acc[p][j], ap[p], bb[j]);
            }
            #pragma unroll
            for (int p = 0; p < 2; ++p)
                #pragma unroll
                for (int j = 0; j < 4; ++j) {
                    u64 r; MUL2(r, acc[p][j], s2);
                    *(u64*)&st[(m0 + j) * 64 + t0 + 2 * p] = r;
                }
        }
    }
    __syncthreads();

    // ================= Softmax over m, per (head, token) column: 256 columns, 1 thread each ==
    {
        const int h = tid >> 6;
        const int t = tid & 63;
        float* col = sm_w + h * 4096 + t;   // stride 64 -> conflict-free column scan
        float mx = -1e30f;
        #pragma unroll 8
        for (int m = 0; m < 64; ++m) mx = fmaxf(mx, col[m * 64]);
        float s = 0.f;
        #pragma unroll 8
        for (int m = 0; m < 64; ++m) {
            float e = __expf(col[m * 64] - mx);
            col[m * 64] = e;
            s += e;
        }
        float inv = 1.0f / s;
        #pragma unroll 8
        for (int m = 0; m < 64; ++m) col[m * 64] *= inv;
    }
    __syncthreads();

    // ================= PV: O^T[d][t] = (P V)^T, all heads fused; K-dim 64 =================
    // microtile: 4t x 8d per thread (d0 stays within one head). O^T written into sm_x.
    {
        const int t0 = (tid >> 4) * 4;
        const int d0 = (tid & 15) * 8;      // 0..120, head = d0>>5
        const float* st = sm_w + (d0 >> 5) * 4096;

        u64 acc[2][8];
        #pragma unroll
        for (int p = 0; p < 2; ++p)
            #pragma unroll
            for (int j = 0; j < 8; ++j) acc[p][j] = 0ull;

        #pragma unroll 4
        for (int m = 0; m < 64; ++m) {
            ulonglong2 pa = *(const ulonglong2*)&st[m * 64 + t0];
            float4 v0 = *(const float4*)&sm_v[m * V_STR + d0];
            float4 v1 = *(const float4*)&sm_v[m * V_STR + d0 + 4];
            u64 bb[8];
            BCAST(bb[0], v0.x); BCAST(bb[1], v0.y); BCAST(bb[2], v0.z); BCAST(bb[3], v0.w);
            BCAST(bb[4], v1.x); BCAST(bb[5], v1.y); BCAST(bb[6], v1.z); BCAST(bb[7], v1.w);
            u64 ap[2] = {pa.x, pa.y};
            #pragma unroll
            for (int p = 0; p < 2; ++p)
                #pragma unroll
                for (int j = 0; j < 8; ++j)
                    FMA2(acc[p][j], ap[p], bb[j]);
        }
        #pragma unroll
        for (int p = 0; p < 2; ++p)
            #pragma unroll
            for (int j = 0; j < 8; ++j)
                *(u64*)&sm_x[(d0 + j) * 64 + t0 + 2 * p] = acc[p][j];
    }
    __syncthreads();   // O^T ready; S^T dead -> sm_w reusable for w_proj

    // ================= Proj: out[t][c] = O^T[k][t] . w_proj[k][c] + b ======================
    // microtile: 8c x 4t per thread; lanes vary along t -> coalesced channel-first store.
    {
        // load w_proj [128][128] into sm_w
        #pragma unroll
        for (int it = 0; it < 16; ++it) {
            int idx = it * 256 + tid;
            int k  = idx >> 5;
            int jq = idx & 31;
            *(float4*)&sm_w[k * 128 + jq * 4] = *(const float4*)&w_proj[k * 128 + jq * 4];
        }
        __syncthreads();

        const int t0 = (tid & 15) * 4;     // lanes -> tokens (coalescing)
        const int c0 = (tid >> 4) * 8;

        u64 acc[8][2];
        #pragma unroll
        for (int c = 0; c < 8; ++c)
            #pragma unroll
            for (int p = 0; p < 2; ++p) acc[c][p] = 0ull;

        #pragma unroll 4
        for (int k = 0; k < 128; ++k) {
            ulonglong2 oa = *(const ulonglong2*)&sm_x[k * 64 + t0];
            float4 w0 = *(const float4*)&sm_w[k * 128 + c0];
            float4 w1 = *(const float4*)&sm_w[k * 128 + c0 + 4];
            u64 bb[8];
            BCAST(bb[0], w0.x); BCAST(bb[1], w0.y); BCAST(bb[2], w0.z); BCAST(bb[3], w0.w);
            BCAST(bb[4], w1.x); BCAST(bb[5], w1.y); BCAST(bb[6], w1.z); BCAST(bb[7], w1.w);
            u64 ap[2] = {oa.x, oa.y};
            #pragma unroll
            for (int c = 0; c < 8; ++c)
                #pragma unroll
                for (int p = 0; p < 2; ++p)
                    FMA2(acc[c][p], ap[p], bb[c]);
        }

        #pragma unroll
        for (int c = 0; c < 8; ++c) {
            int ch = c0 + c;
            float bp = __ldg(&b_proj[ch]);
            #pragma unroll
            for (int p = 0; p < 2; ++p) {
                F2U cv; cv.u = acc[c][p];
                #pragma unroll
                for (int e = 0; e < 2; ++e) {
                    int t  = t0 + 2 * p + e;
                    int gr = (row0 + (t >> 3)) & 255;
                    int gc = (col0 + (t & 7)) & 255;
                    out[(((b * 128 + ch) << 8) + gr) * 256 + gc] = cv.f[e] + bp;
                }
            }
        }
    }
}

extern "C" void kernel_launch(void* const* d_in, const int* in_sizes, int n_in,
                              void* d_out, int out_size)
{
    const float* x      = (const float*)d_in[0];
    const float* w_qkv  = (const float*)d_in[1];
    const float* w_proj = (const float*)d_in[2];
    const float* b_proj = (const float*)d_in[3];
    float* out = (float*)d_out;

    cudaFuncSetAttribute(swin_fused_kernel,
                         cudaFuncAttributeMaxDynamicSharedMemorySize, SMEM_BYTES);

    swin_fused_kernel<<<NWIN, 256, SMEM_BYTES>>>(x, w_qkv, w_proj, b_proj, out);
}

// round 10
// speedup vs baseline: 1.5559x; 1.0295x over previous
#include <cuda_runtime.h>

// SwinStyleAttention fused kernel, fp32 + packed f32x2 FMA, one CTA per 8x8 window.
// Split-K 8x8 microtiles on QKV/proj; all-head-parallel 8x8 scores; 8x8 PV.
// B=8, C=128, H=W=256, WS=8, SS=4, HEADS=4, DH=32, INNER=128, L=64.

#define NWIN  8192
#define ATT_SCALE 0.17677669529663687f  // 32^-0.5

// shared memory layout (floats)
#define XS_SZ  (128*64)     // sm_x  [k][t]  (A for qkv; reused as O^T[d][t] for proj)
#define WW_SZ  (128*128)    // sm_w  [k][j]  weight tile; overlaid by S^T (4 heads x 64x64)
#define QT_SZ  (128*64)     // sm_qt [hd][t]
#define KT_SZ  (128*64)     // sm_kt [hd][t]
#define V_SZ   (64*128)     // sm_v  [m][hd]
#define RED_SZ (32*256)     // sm_red [pj 0..31][slot u64 0..127] split-K reduction buffer
#define SMEM_FLOATS (XS_SZ + WW_SZ + QT_SZ + KT_SZ + V_SZ + RED_SZ)
#define SMEM_BYTES  (SMEM_FLOATS * 4)   // 224 KB

typedef unsigned long long u64;

#define FMA2(acc, aa, bb) \
    asm("fma.rn.f32x2 %0, %1, %2, %0;" : "+l"(acc) : "l"(aa), "l"(bb))
#define MUL2(dst, aa, bb) \
    asm("mul.rn.f32x2 %0, %1, %2;" : "=l"(dst) : "l"(aa), "l"(bb))
#define ADD2(acc, bb) \
    asm("add.rn.f32x2 %0, %0, %1;" : "+l"(acc) : "l"(bb))
#define BCAST(dst, f) \
    asm("mov.b64 %0, {%1, %1};" : "=l"(dst) : "f"(f))

union F2U { u64 u; float f[2]; };

__global__ __launch_bounds__(256, 1)
void swin_fused_kernel(const float* __restrict__ x,
                       const float* __restrict__ w_qkv,
                       const float* __restrict__ w_proj,
                       const float* __restrict__ b_proj,
                       float* __restrict__ out)
{
    extern __shared__ float sm[];
    float* sm_x   = sm;
    float* sm_w   = sm_x  + XS_SZ;   // S^T overlay: head h at sm_w + h*4096, [m][t] stride 64
    float* sm_qt  = sm_w  + WW_SZ;
    float* sm_kt  = sm_qt + QT_SZ;
    float* sm_v   = sm_kt + KT_SZ;
    float* sm_red = sm_v  + V_SZ;

    const int tid = threadIdx.x;
    const int win = blockIdx.x;
    const int b   = win >> 10;
    const int wh  = (win >> 5) & 31;
    const int ww  = win & 31;

    const int row0 = wh * 8 + 4;     // cyclic shift folded into gather/scatter
    const int col0 = ww * 8 + 4;

    // ---- load window x into sm_x[k][t] ----
    #pragma unroll
    for (int it = 0; it < 32; ++it) {
        int idx = it * 256 + tid;     // ch*64 + t
        int ch  = idx >> 6;
        int t   = idx & 63;
        int sr  = (row0 + (t >> 3)) & 255;
        int sc  = (col0 + (t & 7)) & 255;
        sm_x[idx] = x[(((b * 128 + ch) << 8) + sr) * 256 + sc];
    }

    // split-K thread map (QKV & proj): 2 k-groups x 128 slots, 8t x 8j microtile
    const int g     = tid >> 7;          // k-group
    const int slot  = tid & 127;
    const int t0    = (slot & 7) * 8;    // lanes vary along t
    const int j0    = (slot >> 3) * 8;   // 16 j-groups x 8 = 128
    const int kbase = g * 64;

    // ================= QKV GEMM: [64t x 128k] @ [128k x 384], 3 passes of 128j ==========
    for (int jt = 0; jt < 3; ++jt) {
        __syncthreads();
        // load weight tile [128k][128j]
        #pragma unroll
        for (int it = 0; it < 16; ++it) {
            int idx = it * 256 + tid;         // float4 index: k*32 + jq
            int k  = idx >> 5;
            int jq = idx & 31;
            *(float4*)&sm_w[k * 128 + jq * 4] =
                *(const float4*)&w_qkv[k * 384 + jt * 128 + jq * 4];
        }
        __syncthreads();

        u64 acc[4][8];
        #pragma unroll
        for (int p = 0; p < 4; ++p)
            #pragma unroll
            for (int j = 0; j < 8; ++j) acc[p][j] = 0ull;

        #pragma unroll 4
        for (int kk = 0; kk < 64; ++kk) {
            int k = kbase + kk;
            ulonglong2 A0 = *(const ulonglong2*)&sm_x[k * 64 + t0];
            ulonglong2 A1 = *(const ulonglong2*)&sm_x[k * 64 + t0 + 4];
            float4 w0 = *(const float4*)&sm_w[k * 128 + j0];
            float4 w1 = *(const float4*)&sm_w[k * 128 + j0 + 4];
            u64 bb[8];
            BCAST(bb[0], w0.x); BCAST(bb[1], w0.y); BCAST(bb[2], w0.z); BCAST(bb[3], w0.w);
            BCAST(bb[4], w1.x); BCAST(bb[5], w1.y); BCAST(bb[6], w1.z); BCAST(bb[7], w1.w);
            u64 ap[4] = {A0.x, A0.y, A1.x, A1.y};
            #pragma unroll
            for (int p = 0; p < 4; ++p)
                #pragma unroll
                for (int j = 0; j < 8; ++j)
                    FMA2(acc[p][j], ap[p], bb[j]);
        }

        // split-K reduce: group1 stages partials ([pj][slot] -> coalesced), group0 merges
        if (g == 1) {
            #pragma unroll
            for (int p = 0; p < 4; ++p)
                #pragma unroll
                for (int j = 0; j < 8; ++j)
                    *(u64*)&sm_red[(p * 8 + j) * 256 + slot * 2] = acc[p][j];
        }
        __syncthreads();
        if (g == 0) {
            #pragma unroll
            for (int p = 0; p < 4; ++p)
                #pragma unroll
                for (int j = 0; j < 8; ++j) {
                    u64 o = *(const u64*)&sm_red[(p * 8 + j) * 256 + slot * 2];
                    ADD2(acc[p][j], o);
                }
            if (jt == 0) {            // Q^T[hd][t]
                #pragma unroll
                for (int p = 0; p < 4; ++p)
                    #pragma unroll
                    for (int j = 0; j < 8; ++j)
                        *(u64*)&sm_qt[(j0 + j) * 64 + t0 + 2 * p] = acc[p][j];
            } else if (jt == 1) {     // K^T[hd][t]
                #pragma unroll
                for (int p = 0; p < 4; ++p)
                    #pragma unroll
                    for (int j = 0; j < 8; ++j)
                        *(u64*)&sm_kt[(j0 + j) * 64 + t0 + 2 * p] = acc[p][j];
            } else {                  // V[m][hd]  (scatter unpack)
                #pragma unroll
                for (int p = 0; p < 4; ++p)
                    #pragma unroll
                    for (int j = 0; j < 8; ++j) {
                        F2U cv; cv.u = acc[p][j];
                        sm_v[(t0 + 2 * p)     * 128 + j0 + j] = cv.f[0];
                        sm_v[(t0 + 2 * p + 1) * 128 + j0 + j] = cv.f[1];
                    }
            }
        }
    }
    __syncthreads();   // qt/kt/v ready; sm_w free for S^T

    // ================= Scores: S^T[h][m][t] = (Q K^T)^T * SCALE, all heads in parallel ====
    // thread -> (head = tid>>6, 8t x 8m microtile within head); K-dim 32.
    {
        const int h   = tid >> 6;
        const int s6  = tid & 63;
        const int st0 = (s6 & 7) * 8;
        const int sm0 = (s6 >> 3) * 8;
        const int hd0 = h * 32;
        float* st = sm_w + h * 4096;
        u64 s2; BCAST(s2, ATT_SCALE);

        u64 acc[4][8];
        #pragma unroll
        for (int p = 0; p < 4; ++p)
            #pragma unroll
            for (int j = 0; j < 8; ++j) acc[p][j] = 0ull;

        #pragma unroll 4
        for (int d = 0; d < 32; ++d) {
            ulonglong2 q0 = *(const ulonglong2*)&sm_qt[(hd0 + d) * 64 + st0];
            ulonglong2 q1 = *(const ulonglong2*)&sm_qt[(hd0 + d) * 64 + st0 + 4];
            float4 k0v = *(const float4*)&sm_kt[(hd0 + d) * 64 + sm0];
            float4 k1v = *(const float4*)&sm_kt[(hd0 + d) * 64 + sm0 + 4];
            u64 bb[8];
            BCAST(bb[0], k0v.x); BCAST(bb[1], k0v.y); BCAST(bb[2], k0v.z); BCAST(bb[3], k0v.w);
            BCAST(bb[4], k1v.x); BCAST(bb[5], k1v.y); BCAST(bb[6], k1v.z); BCAST(bb[7], k1v.w);
            u64 ap[4] = {q0.x, q0.y, q1.x, q1.y};
            #pragma unroll
            for (int p = 0; p < 4; ++p)
                #pragma unroll
                for (int j = 0; j < 8; ++j)
                    FMA2(acc[p][j], ap[p], bb[j]);
        }
        #pragma unroll
        for (int p = 0; p < 4; ++p)
            #pragma unroll
            for (int j = 0; j < 8; ++j) {
                u64 r; MUL2(r, acc[p][j], s2);
                *(u64*)&st[(sm0 + j) * 64 + st0 + 2 * p] = r;
            }
    }
    __syncthreads();

    // ================= Softmax over m, per (head, token) column: 256 columns ==============
    {
        const int h = tid >> 6;
        const int t = tid & 63;
        float* col = sm_w + h * 4096 + t;   // stride 64 -> conflict-free column scan
        float mx = -1e30f;
        #pragma unroll 8
        for (int m = 0; m < 64; ++m) mx = fmaxf(mx, col[m * 64]);
        float s = 0.f;
        #pragma unroll 8
        for (int m = 0; m < 64; ++m) {
            float e = __expf(col[m * 64] - mx);
            col[m * 64] = e;
            s += e;
        }
        float inv = 1.0f / s;
        #pragma unroll 8
        for (int m = 0; m < 64; ++m) col[m * 64] *= inv;
    }
    __syncthreads();

    // ================= PV: O^T[d][t] = (P V)^T; 128 threads, 8t x 8d microtile ============
    if (tid < 128) {
        const int pt0 = (tid & 7) * 8;
        const int d0  = (tid >> 3) * 8;     // 16 d-groups x 8 = 128, head = d0>>5
        const float* st = sm_w + (d0 >> 5) * 4096;

        u64 acc[4][8];
        #pragma unroll
        for (int p = 0; p < 4; ++p)
            #pragma unroll
            for (int j = 0; j < 8; ++j) acc[p][j] = 0ull;

        #pragma unroll 4
        for (int m = 0; m < 64; ++m) {
            ulonglong2 p0 = *(const ulonglong2*)&st[m * 64 + pt0];
            ulonglong2 p1 = *(const ulonglong2*)&st[m * 64 + pt0 + 4];
            float4 v0 = *(const float4*)&sm_v[m * 128 + d0];
            float4 v1 = *(const float4*)&sm_v[m * 128 + d0 + 4];
            u64 bb[8];
            BCAST(bb[0], v0.x); BCAST(bb[1], v0.y); BCAST(bb[2], v0.z); BCAST(bb[3], v0.w);
            BCAST(bb[4], v1.x); BCAST(bb[5], v1.y); BCAST(bb[6], v1.z); BCAST(bb[7], v1.w);
            u64 ap[4] = {p0.x, p0.y, p1.x, p1.y};
            #pragma unroll
            for (int p = 0; p < 4; ++p)
                #pragma unroll
                for (int j = 0; j < 8; ++j)
                    FMA2(acc[p][j], ap[p], bb[j]);
        }
        #pragma unroll
        for (int p = 0; p < 4; ++p)
            #pragma unroll
            for (int j = 0; j < 8; ++j)
                *(u64*)&sm_x[(d0 + j) * 64 + pt0 + 2 * p] = acc[p][j];
    }
    __syncthreads();   // O^T ready; S^T dead -> sm_w reusable for w_proj

    // ================= Proj: out = O^T . w_proj + b, split-K 8t x 8c ======================
    {
        // load w_proj [128][128] into sm_w
        #pragma unroll
        for (int it = 0; it < 16; ++it) {
            int idx = it * 256 + tid;
            int k  = idx >> 5;
            int jq = idx & 31;
            *(float4*)&sm_w[k * 128 + jq * 4] = *(const float4*)&w_proj[k * 128 + jq * 4];
        }
        __syncthreads();

        const int c0 = j0;                  // 8 channels per thread

        u64 acc[4][8];
        #pragma unroll
        for (int p = 0; p < 4; ++p)
            #pragma unroll
            for (int j = 0; j < 8; ++j) acc[p][j] = 0ull;

        #pragma unroll 4
        for (int kk = 0; kk < 64; ++kk) {
            int k = kbase + kk;
            ulonglong2 o0 = *(const ulonglong2*)&sm_x[k * 64 + t0];
            ulonglong2 o1 = *(const ulonglong2*)&sm_x[k * 64 + t0 + 4];
            float4 w0 = *(const float4*)&sm_w[k * 128 + c0];
            float4 w1 = *(const float4*)&sm_w[k * 128 + c0 + 4];
            u64 bb[8];
            BCAST(bb[0], w0.x); BCAST(bb[1], w0.y); BCAST(bb[2], w0.z); BCAST(bb[3], w0.w);
            BCAST(bb[4], w1.x); BCAST(bb[5], w1.y); BCAST(bb[6], w1.z); BCAST(bb[7], w1.w);
            u64 ap[4] = {o0.x, o0.y, o1.x, o1.y};
            #pragma unroll
            for (int p = 0; p < 4; ++p)
                #pragma unroll
                for (int j = 0; j < 8; ++j)
                    FMA2(acc[p][j], ap[p], bb[j]);
        }

        if (g == 1) {
            #pragma unroll
            for (int p = 0; p < 4; ++p)
                #pragma unroll
                for (int j = 0; j < 8; ++j)
                    *(u64*)&sm_red[(p * 8 + j) * 256 + slot * 2] = acc[p][j];
        }
        __syncthreads();
        if (g == 0) {
            #pragma unroll
            for (int p = 0; p < 4; ++p)
                #pragma unroll
                for (int j = 0; j < 8; ++j) {
                    u64 o = *(const u64*)&sm_red[(p * 8 + j) * 256 + slot * 2];
                    ADD2(acc[p][j], o);
                }
            const int gr = (row0 + (t0 >> 3)) & 255;   // t0..t0+7 share one window row
            #pragma unroll
            for (int j = 0; j < 8; ++j) {
                int ch = c0 + j;
                float bp = __ldg(&b_proj[ch]);
                float* ob = &out[(((b * 128 + ch) << 8) + gr) * 256];
                #pragma unroll
                for (int p = 0; p < 4; ++p) {
                    F2U cv; cv.u = acc[p][j];
                    #pragma unroll
                    for (int e = 0; e < 2; ++e) {
                        int gc = (col0 + 2 * p + e) & 255;
                        ob[gc] = cv.f[e] + bp;
                    }
                }
            }
        }
    }
}

extern "C" void kernel_launch(void* const* d_in, const int* in_sizes, int n_in,
                              void* d_out, int out_size)
{
    const float* x      = (const float*)d_in[0];
    const float* w_qkv  = (const float*)d_in[1];
    const float* w_proj = (const float*)d_in[2];
    const float* b_proj = (const float*)d_in[3];
    float* out = (float*)d_out;

    cudaFuncSetAttribute(swin_fused_kernel,
                         cudaFuncAttributeMaxDynamicSharedMemorySize, SMEM_BYTES);

    swin_fused_kernel<<<NWIN, 256, SMEM_BYTES>>>(x, w_qkv, w_proj, b_proj, out);
}

// round 12
// speedup vs baseline: 3.3715x; 2.1669x over previous
#include <cuda_runtime.h>
#include <cuda_fp16.h>

// SwinStyleAttention: HMMA (mma.sync m16n8k16 fp16) for qkv+proj GEMMs,
// fp32 CUDA-core attention (R10 structure). One CTA per 8x8 window.
// B=8, C=128, H=W=256, WS=8, SS=4, HEADS=4, DH=32, INNER=128, L=64.

#define NWIN  8192
#define ATT_SCALE 0.17677669529663687f

typedef unsigned long long u64;
typedef unsigned int u32;

// ---- SMEM byte layout (217088 B total) ----
#define SM_A   0         // fp16 [64t][136] : X for qkv A; reused as O (proj A)
#define SM_B   17408     // fp16 [128n][136]: weight tile (B operand, [n][k])
#define SM_QT  52224     // fp32 [128d][64t]
#define SM_KT  84992     // fp32 [128d][64t]
#define SM_S   117760    // fp32 4 heads x [64m][64t]
#define SM_V   183296    // fp32 [64m][132d]
#define V_STR  132
#define SMEM_BYTES 217088
#define SAB 136          // half stride of SM_A / SM_B rows (272 B, 16B-aligned)

// ---- fp32x2 packed-FMA helpers (attention mainloops) ----
#define FMA2(acc, aa, bb) \
    asm("fma.rn.f32x2 %0, %1, %2, %0;" : "+l"(acc) : "l"(aa), "l"(bb))
#define MUL2(dst, aa, bb) \
    asm("mul.rn.f32x2 %0, %1, %2;" : "=l"(dst) : "l"(aa), "l"(bb))
#define BCAST(dst, f) \
    asm("mov.b64 %0, {%1, %1};" : "=l"(dst) : "f"(f))
union F2U { u64 u; float f[2]; };

// ---- HMMA helpers (sm_80-era, valid on compute_103) ----
__device__ __forceinline__ u32 smem_u32(const void* p) {
    u32 a;
    asm("{ .reg .u64 t; cvta.to.shared.u64 t, %1; cvt.u32.u64 %0, t; }" : "=r"(a) : "l"(p));
    return a;
}
__device__ __forceinline__ void ldsm4(u32* r, u32 addr) {
    asm volatile("ldmatrix.sync.aligned.m8n8.x4.shared.b16 {%0,%1,%2,%3}, [%4];"
        : "=r"(r[0]), "=r"(r[1]), "=r"(r[2]), "=r"(r[3]) : "r"(addr));
}
__device__ __forceinline__ void mma16816(float* c, const u32* a, u32 b0, u32 b1) {
    asm volatile("mma.sync.aligned.m16n8k16.row.col.f32.f16.f16.f32 "
        "{%0,%1,%2,%3}, {%4,%5,%6,%7}, {%8,%9}, {%0,%1,%2,%3};"
        : "+f"(c[0]), "+f"(c[1]), "+f"(c[2]), "+f"(c[3])
        : "r"(a[0]), "r"(a[1]), "r"(a[2]), "r"(a[3]), "r"(b0), "r"(b1));
}

// GEMM core: D[64m x 128n] += A[64x128] * B^T, A at SM_A, B([n][k]) at SM_B.
// 8 warps as 2M x 4N -> 32x32 warp tile; acc[2 mt][4 nt][4].
__device__ __forceinline__ void hmma_64x128x128(u32 smem_base, int warp, int lane,
                                                float acc[2][4][4]) {
    const int wm = (warp >> 2) * 32;
    const int wn = (warp & 3) * 32;
    const u32 a_base = smem_base + SM_A +
        (((wm + (lane & 15)) * SAB + ((lane >> 4) << 3)) << 1);
    const u32 b_base = smem_base + SM_B +
        (((wn + (lane & 15)) * SAB + ((lane >> 4) << 3)) << 1);

    #pragma unroll
    for (int ks = 0; ks < 8; ++ks) {
        const u32 ko = (u32)(ks * 32);           // 16 halfs = 32 B
        u32 a[2][4], bf[2][4];
        ldsm4(a[0],  a_base + ko);
        ldsm4(a[1],  a_base + 16 * SAB * 2 + ko);
        ldsm4(bf[0], b_base + ko);
        ldsm4(bf[1], b_base + 16 * SAB * 2 + ko);
        #pragma unroll
        for (int mt = 0; mt < 2; ++mt)
            #pragma unroll
            for (int nt = 0; nt < 4; ++nt)
                mma16816(acc[mt][nt], a[mt], bf[nt >> 1][nt & 1], bf[nt >> 1][2 + (nt & 1)]);
    }
}

// ---- prebuilt transposed fp16 weight images ----
__device__ __align__(16) __half g_wqkvT[384 * 128];   // [j][k] : row j = output col
__device__ __align__(16) __half g_wprojT[128 * 128];  // [c][d]

__global__ void prep_weights(const float* __restrict__ w_qkv, const float* __restrict__ w_proj)
{
    int r = blockIdx.x, k = threadIdx.x;
    if (r < 384) g_wqkvT[r * 128 + k] = __float2half_rn(w_qkv[k * 384 + r]);
    else         g_wprojT[(r - 384) * 128 + k] = __float2half_rn(w_proj[k * 128 + (r - 384)]);
}

// ---- main fused kernel ----
__global__ __launch_bounds__(256, 1)
void swin_fused_kernel(const float* __restrict__ x,
                       const float* __restrict__ b_proj,
                       float* __restrict__ out)
{
    extern __shared__ unsigned char smb[];
    __half* sm_a  = (__half*)(smb + SM_A);
    float*  sm_qt = (float*)(smb + SM_QT);
    float*  sm_kt = (float*)(smb + SM_KT);
    float*  sm_s  = (float*)(smb + SM_S);
    float*  sm_v  = (float*)(smb + SM_V);
    const u32 smem_base = smem_u32(smb);

    const int tid  = threadIdx.x;
    const int warp = tid >> 5;
    const int lane = tid & 31;
    const int gid  = lane >> 2;
    const int tig  = lane & 3;

    const int win = blockIdx.x;
    const int b   = win >> 10;
    const int wh  = (win >> 5) & 31;
    const int ww  = win & 31;
    const int row0 = wh * 8 + 4;         // cyclic shift folded in
    const int col0 = ww * 8 + 4;

    // ---- gather X -> sm_a[t][c] fp16 ----
    #pragma unroll
    for (int it = 0; it < 32; ++it) {
        int idx = it * 256 + tid;        // ch*64 + t
        int ch  = idx >> 6;
        int t   = idx & 63;
        int gr  = (row0 + (t >> 3)) & 255;
        int gc  = (col0 + (t & 7)) & 255;
        sm_a[t * SAB + ch] = __float2half_rn(x[(((b * 128 + ch) << 8) + gr) * 256 + gc]);
    }

    // ================= QKV: 3 HMMA passes (Q, K, V), each 64x128x128 =================
    for (int p = 0; p < 3; ++p) {
        __syncthreads();
        {   // load weight tile rows [p*128, p*128+128) -> sm_b
            const float4* src = (const float4*)(g_wqkvT + p * 128 * 128);
            #pragma unroll
            for (int it = 0; it < 8; ++it) {
                int idx = it * 256 + tid;            // 2048 float4
                int j = idx >> 4, q = idx & 15;
                *(float4*)(smb + SM_B + (j * SAB + q * 8) * 2) = src[idx];
            }
        }
        __syncthreads();

        float acc[2][4][4];
        #pragma unroll
        for (int mt = 0; mt < 2; ++mt)
            #pragma unroll
            for (int nt = 0; nt < 4; ++nt)
                #pragma unroll
                for (int i = 0; i < 4; ++i) acc[mt][nt][i] = 0.f;

        hmma_64x128x128(smem_base, warp, lane, acc);

        const int wm = (warp >> 2) * 32;
        const int wn = (warp & 3) * 32;
        #pragma unroll
        for (int mt = 0; mt < 2; ++mt)
            #pragma unroll
            for (int nt = 0; nt < 4; ++nt) {
                int m = wm + mt * 16 + gid;          // token
                int n = wn + nt * 8 + 2 * tig;       // qkv column
                float* ap = acc[mt][nt];
                if (p == 0) {                        // Q^T[d][t]
                    sm_qt[n * 64 + m]           = ap[0];
                    sm_qt[(n + 1) * 64 + m]     = ap[1];
                    sm_qt[n * 64 + m + 8]       = ap[2];
                    sm_qt[(n + 1) * 64 + m + 8] = ap[3];
                } else if (p == 1) {                 // K^T[d][t]
                    sm_kt[n * 64 + m]           = ap[0];
                    sm_kt[(n + 1) * 64 + m]     = ap[1];
                    sm_kt[n * 64 + m + 8]       = ap[2];
                    sm_kt[(n + 1) * 64 + m + 8] = ap[3];
                } else {                             // V[m][d]
                    sm_v[m * V_STR + n]           = ap[0];
                    sm_v[m * V_STR + n + 1]       = ap[1];
                    sm_v[(m + 8) * V_STR + n]     = ap[2];
                    sm_v[(m + 8) * V_STR + n + 1] = ap[3];
                }
            }
    }
    __syncthreads();

    // ================= Scores: S^T[h][m][t] = (Q K^T)^T * SCALE (fp32, R10) ==========
    {
        const int h   = tid >> 6;
        const int s6  = tid & 63;
        const int st0 = (s6 & 7) * 8;
        const int sm0 = (s6 >> 3) * 8;
        const int hd0 = h * 32;
        float* st = sm_s + h * 4096;
        u64 s2; BCAST(s2, ATT_SCALE);

        u64 acc[4][8];
        #pragma unroll
        for (int p = 0; p < 4; ++p)
            #pragma unroll
            for (int j = 0; j < 8; ++j) acc[p][j] = 0ull;

        #pragma unroll 4
        for (int d = 0; d < 32; ++d) {
            ulonglong2 q0 = *(const ulonglong2*)&sm_qt[(hd0 + d) * 64 + st0];
            ulonglong2 q1 = *(const ulonglong2*)&sm_qt[(hd0 + d) * 64 + st0 + 4];
            float4 k0v = *(const float4*)&sm_kt[(hd0 + d) * 64 + sm0];
            float4 k1v = *(const float4*)&sm_kt[(hd0 + d) * 64 + sm0 + 4];
            u64 bb[8];
            BCAST(bb[0], k0v.x); BCAST(bb[1], k0v.y); BCAST(bb[2], k0v.z); BCAST(bb[3], k0v.w);
            BCAST(bb[4], k1v.x); BCAST(bb[5], k1v.y); BCAST(bb[6], k1v.z); BCAST(bb[7], k1v.w);
            u64 ap[4] = {q0.x, q0.y, q1.x, q1.y};
            #pragma unroll
            for (int p = 0; p < 4; ++p)
                #pragma unroll
                for (int j = 0; j < 8; ++j)
                    FMA2(acc[p][j], ap[p], bb[j]);
        }
        #pragma unroll
        for (int p = 0; p < 4; ++p)
            #pragma unroll
            for (int j = 0; j < 8; ++j) {
                u64 rr; MUL2(rr, acc[p][j], s2);
                *(u64*)&st[(sm0 + j) * 64 + st0 + 2 * p] = rr;
            }
    }
    __syncthreads();

    // ================= Softmax over m per (head, token) column =================
    {
        const int h = tid >> 6;
        const int t = tid & 63;
        float* col = sm_s + h * 4096 + t;
        float mx = -1e30f;
        #pragma unroll 8
        for (int m = 0; m < 64; ++m) mx = fmaxf(mx, col[m * 64]);
        float s = 0.f;
        #pragma unroll 8
        for (int m = 0; m < 64; ++m) {
            float e = __expf(col[m * 64] - mx);
            col[m * 64] = e;
            s += e;
        }
        float inv = 1.0f / s;
        #pragma unroll 8
        for (int m = 0; m < 64; ++m) col[m * 64] *= inv;
    }
    __syncthreads();

    // ================= PV: O[t][d] fp16 (proj A tile) ; 128 threads, 8t x 8d =========
    if (tid < 128) {
        const int pt0 = (tid & 7) * 8;
        const int d0  = (tid >> 3) * 8;
        const float* st = sm_s + (d0 >> 5) * 4096;

        u64 acc[4][8];
        #pragma unroll
        for (int p = 0; p < 4; ++p)
            #pragma unroll
            for (int j = 0; j < 8; ++j) acc[p][j] = 0ull;

        #pragma unroll 4
        for (int m = 0; m < 64; ++m) {
            ulonglong2 p0 = *(const ulonglong2*)&st[m * 64 + pt0];
            ulonglong2 p1 = *(const ulonglong2*)&st[m * 64 + pt0 + 4];
            float4 v0 = *(const float4*)&sm_v[m * V_STR + d0];
            float4 v1 = *(const float4*)&sm_v[m * V_STR + d0 + 4];
            u64 bb[8];
            BCAST(bb[0], v0.x); BCAST(bb[1], v0.y); BCAST(bb[2], v0.z); BCAST(bb[3], v0.w);
            BCAST(bb[4], v1.x); BCAST(bb[5], v1.y); BCAST(bb[6], v1.z); BCAST(bb[7], v1.w);
            u64 ap[4] = {p0.x, p0.y, p1.x, p1.y};
            #pragma unroll
            for (int p = 0; p < 4; ++p)
                #pragma unroll
                for (int j = 0; j < 8; ++j)
                    FMA2(acc[p][j], ap[p], bb[j]);
        }
        // transpose-in-regs -> fp16 row-major O[t][d] into sm_a
        #pragma unroll
        for (int tt = 0; tt < 8; ++tt) {
            int tok = pt0 + tt;
            #pragma unroll
            for (int i = 0; i < 4; ++i) {
                F2U c0; c0.u = acc[tt >> 1][2 * i];
                F2U c1; c1.u = acc[tt >> 1][2 * i + 1];
                __half2 h2 = __floats2half2_rn(c0.f[tt & 1], c1.f[tt & 1]);
                *(u32*)&sm_a[tok * SAB + d0 + 2 * i] = *(u32*)&h2;
            }
        }
    }
    __syncthreads();

    // ================= Proj: HMMA 64x128x128, then coalesced epilogue =================
    {   // load w_projT image -> sm_b
        const float4* src = (const float4*)g_wprojT;
        #pragma unroll
        for (int it = 0; it < 8; ++it) {
            int idx = it * 256 + tid;
            int j = idx >> 4, q = idx & 15;
            *(float4*)(smb + SM_B + (j * SAB + q * 8) * 2) = src[idx];
        }
    }
    __syncthreads();

    {
        float acc[2][4][4];
        #pragma unroll
        for (int mt = 0; mt < 2; ++mt)
            #pragma unroll
            for (int nt = 0; nt < 4; ++nt)
                #pragma unroll
                for (int i = 0; i < 4; ++i) acc[mt][nt][i] = 0.f;

        hmma_64x128x128(smem_base, warp, lane, acc);

        // frags -> sm_final[c][t] (reuse QT region)
        float* sm_final = sm_qt;
        const int wm = (warp >> 2) * 32;
        const int wn = (warp & 3) * 32;
        #pragma unroll
        for (int mt = 0; mt < 2; ++mt)
            #pragma unroll
            for (int nt = 0; nt < 4; ++nt) {
                int m = wm + mt * 16 + gid;          // token
                int n = wn + nt * 8 + 2 * tig;       // channel
                float* ap = acc[mt][nt];
                sm_final[n * 64 + m]           = ap[0];
                sm_final[(n + 1) * 64 + m]     = ap[1];
                sm_final[n * 64 + m + 8]       = ap[2];
                sm_final[(n + 1) * 64 + m + 8] = ap[3];
            }
    }
    __syncthreads();

    // epilogue: coalesced channel-first store with bias
    {
        const float* sm_final = sm_qt;
        #pragma unroll
        for (int it = 0; it < 32; ++it) {
            int idx = it * 256 + tid;
            int c = idx >> 6;
            int t = idx & 63;
            int gr = (row0 + (t >> 3)) & 255;
            int gc = (col0 + (t & 7)) & 255;
            out[(((b * 128 + c) << 8) + gr) * 256 + gc] =
                sm_final[c * 64 + t] + __ldg(&b_proj[c]);
        }
    }
}

extern "C" void kernel_launch(void* const* d_in, const int* in_sizes, int n_in,
                              void* d_out, int out_size)
{
    const float* x      = (const float*)d_in[0];
    const float* w_qkv  = (const float*)d_in[1];
    const float* w_proj = (const float*)d_in[2];
    const float* b_proj = (const float*)d_in[3];
    float* out = (float*)d_out;

    prep_weights<<<512, 128>>>(w_qkv, w_proj);

    cudaFuncSetAttribute(swin_fused_kernel,
                         cudaFuncAttributeMaxDynamicSharedMemorySize, SMEM_BYTES);
    swin_fused_kernel<<<NWIN, 256, SMEM_BYTES>>>(x, b_proj, out);
}

// round 16
// speedup vs baseline: 3.4550x; 1.0248x over previous
#include <cuda_runtime.h>
#include <cuda_fp16.h>

// SwinStyleAttention: HMMA (mma.sync m16n8k16 fp16) for qkv+proj GEMMs,
// fp32 CUDA-core attention. One CTA per 8x8 window, 512 threads,
// cp.async-pipelined weight tiles.
// B=8, C=128, H=W=256, WS=8, SS=4, HEADS=4, DH=32, INNER=128, L=64.

#define NWIN  8192
#define NT    512
#define ATT_SCALE 0.17677669529663687f

typedef unsigned long long u64;
typedef unsigned int u32;

// ---- SMEM byte layout (217088 B total) ----
#define SM_A   0         // fp16 [64t][136] : X for qkv A; reused as O (proj A)
#define SM_B   17408     // fp16 [128n][136]: weight tile buffer 0
#define SM_QT  52224     // fp32 [128d][64t]
#define SM_KT  84992     // fp32 [128d][64t]
#define SM_S   117760    // fp32 4 heads x [64m][64t]; SM_BB overlays (tile1)
#define SM_BB  117760    // fp16 [128n][136] weight tile buffer 1 (dead before scores)
#define SM_V   183296    // fp32 [64m][132d]
#define V_STR  132
#define SMEM_BYTES 217088
#define SAB 136          // half stride of SM_A / SM_B rows (272 B = 17 x 16B)

// ---- fp32x2 packed-FMA helpers (attention mainloops) ----
#define FMA2(acc, aa, bb) \
    asm("fma.rn.f32x2 %0, %1, %2, %0;" : "+l"(acc) : "l"(aa), "l"(bb))
#define MUL2(dst, aa, bb) \
    asm("mul.rn.f32x2 %0, %1, %2;" : "=l"(dst) : "l"(aa), "l"(bb))
#define BCAST(dst, f) \
    asm("mov.b64 %0, {%1, %1};" : "=l"(dst) : "f"(f))
union F2U { u64 u; float f[2]; };

// ---- cp.async ----
#define CP16(dst, src) \
    asm volatile("cp.async.cg.shared.global [%0], [%1], 16;" :: "r"(dst), "l"(src))
#define CP_COMMIT() asm volatile("cp.async.commit_group;" ::: "memory")
#define CP_WAIT(n)  asm volatile("cp.async.wait_group %0;" :: "n"(n) : "memory")

// ---- HMMA helpers ----
__device__ __forceinline__ u32 smem_u32(const void* p) {
    u32 a;
    asm("{ .reg .u64 t; cvta.to.shared.u64 t, %1; cvt.u32.u64 %0, t; }" : "=r"(a) : "l"(p));
    return a;
}
__device__ __forceinline__ void ldsm4(u32* r, u32 addr) {
    asm volatile("ldmatrix.sync.aligned.m8n8.x4.shared.b16 {%0,%1,%2,%3}, [%4];"
        : "=r"(r[0]), "=r"(r[1]), "=r"(r[2]), "=r"(r[3]) : "r"(addr));
}
__device__ __forceinline__ void mma16816(float* c, const u32* a, u32 b0, u32 b1) {
    asm volatile("mma.sync.aligned.m16n8k16.row.col.f32.f16.f16.f32 "
        "{%0,%1,%2,%3}, {%4,%5,%6,%7}, {%8,%9}, {%0,%1,%2,%3};"
        : "+f"(c[0]), "+f"(c[1]), "+f"(c[2]), "+f"(c[3])
        : "r"(a[0]), "r"(a[1]), "r"(a[2]), "r"(a[3]), "r"(b0), "r"(b1));
}

// GEMM core (16 warps): D[64m x 128n] += A[64x128] * B^T. Warp tile 16m x 32n.
__device__ __forceinline__ void hmma512(u32 smem_base, u32 b_off, int warp, int lane,
                                        float acc[4][4]) {
    const int wm = (warp >> 2) * 16;
    const int wn = (warp & 3) * 32;
    const u32 a_base = smem_base + SM_A +
        (((wm + (lane & 15)) * SAB + ((lane >> 4) << 3)) << 1);
    const u32 b_base = smem_base + b_off +
        (((wn + (lane & 15)) * SAB + ((lane >> 4) << 3)) << 1);

    #pragma unroll
    for (int ks = 0; ks < 8; ++ks) {
        const u32 ko = (u32)(ks * 32);
        u32 a[4], bf[2][4];
        ldsm4(a,     a_base + ko);
        ldsm4(bf[0], b_base + ko);
        ldsm4(bf[1], b_base + 16 * SAB * 2 + ko);
        #pragma unroll
        for (int nt = 0; nt < 4; ++nt)
            mma16816(acc[nt], a, bf[nt >> 1][nt & 1], bf[nt >> 1][2 + (nt & 1)]);
    }
}

// ---- prebuilt transposed fp16 weight images ----
__device__ __align__(16) __half g_wqkvT[384 * 128];   // [j][k]
__device__ __align__(16) __half g_wprojT[128 * 128];  // [c][d]

__global__ void prep_weights(const float* __restrict__ w_qkv, const float* __restrict__ w_proj)
{
    int r = blockIdx.x, k = threadIdx.x;
    if (r < 384) g_wqkvT[r * 128 + k] = __float2half_rn(w_qkv[k * 384 + r]);
    else         g_wprojT[(r - 384) * 128 + k] = __float2half_rn(w_proj[k * 128 + (r - 384)]);
}

// prefetch a [128n x 128k] fp16 weight image into smem tile (stride SAB)
__device__ __forceinline__ void prefetch_tile(u32 smem_base, u32 off, const __half* src, int tid) {
    #pragma unroll
    for (int i = 0; i < 4; ++i) {
        int idx = i * NT + tid;          // 2048 16B-chunks
        int r = idx >> 4;
        int c = (idx & 15) << 3;
        CP16(smem_base + off + (r * SAB + c) * 2, src + r * 128 + c);
    }
}

// ---- main fused kernel ----
__global__ __launch_bounds__(NT, 1)
void swin_fused_kernel(const float* __restrict__ x,
                       const float* __restrict__ b_proj,
                       float* __restrict__ out)
{
    extern __shared__ unsigned char smb[];
    __half* sm_a  = (__half*)(smb + SM_A);
    float*  sm_qt = (float*)(smb + SM_QT);
    float*  sm_kt = (float*)(smb + SM_KT);
    float*  sm_s  = (float*)(smb + SM_S);
    float*  sm_v  = (float*)(smb + SM_V);
    const u32 smem_base = smem_u32(smb);

    const int tid  = threadIdx.x;
    const int warp = tid >> 5;
    const int lane = tid & 31;
    const int gid  = lane >> 2;
    const int tig  = lane & 3;

    const int win = blockIdx.x;
    const int b   = win >> 10;
    const int wh  = (win >> 5) & 31;
    const int ww  = win & 31;
    const int row0 = wh * 8 + 4;
    const int col0 = ww * 8 + 4;

    // ---- prefetch qkv tile0 (Q weights) ----
    prefetch_tile(smem_base, SM_B, g_wqkvT, tid);
    CP_COMMIT();                                       // g0

    // ---- gather X -> sm_a[t][c] fp16 (overlapped with tile0 in flight) ----
    #pragma unroll
    for (int it = 0; it < 16; ++it) {
        int idx = it * NT + tid;         // ch*64 + t
        int ch  = idx >> 6;
        int t   = idx & 63;
        int gr  = (row0 + (t >> 3)) & 255;
        int gc  = (col0 + (t & 7)) & 255;
        sm_a[t * SAB + ch] = __float2half_rn(x[(((b * 128 + ch) << 8) + gr) * 256 + gc]);
    }

    // ---- prefetch tile1 (K weights) into SM_BB ----
    prefetch_tile(smem_base, SM_BB, g_wqkvT + 128 * 128, tid);
    CP_COMMIT();                                       // g1
    CP_WAIT(1);                                        // tile0 ready
    __syncthreads();

    // ================= pass 0: Q = X Wq^T =================
    {
        float acc[4][4];
        #pragma unroll
        for (int nt = 0; nt < 4; ++nt)
            #pragma unroll
            for (int i = 0; i < 4; ++i) acc[nt][i] = 0.f;
        hmma512(smem_base, SM_B, warp, lane, acc);

        const int m0 = (warp >> 2) * 16 + gid;
        const int wn = (warp & 3) * 32;
        #pragma unroll
        for (int nt = 0; nt < 4; ++nt) {
            int n = wn + nt * 8 + 2 * tig;
            sm_qt[n * 64 + m0]           = acc[nt][0];
            sm_qt[(n + 1) * 64 + m0]     = acc[nt][1];
            sm_qt[n * 64 + m0 + 8]       = acc[nt][2];
            sm_qt[(n + 1) * 64 + m0 + 8] = acc[nt][3];
        }
    }
    __syncthreads();                                   // all warps done with SM_B

    // ---- prefetch tile2 (V weights) back into SM_B ----
    prefetch_tile(smem_base, SM_B, g_wqkvT + 2 * 128 * 128, tid);
    CP_COMMIT();                                       // g2
    CP_WAIT(1);                                        // tile1 ready
    __syncthreads();

    // ================= pass 1: K = X Wk^T (reads SM_BB) =================
    {
        float acc[4][4];
        #pragma unroll
        for (int nt = 0; nt < 4; ++nt)
            #pragma unroll
            for (int i = 0; i < 4; ++i) acc[nt][i] = 0.f;
        hmma512(smem_base, SM_BB, warp, lane, acc);

        const int m0 = (warp >> 2) * 16 + gid;
        const int wn = (warp & 3) * 32;
        #pragma unroll
        for (int nt = 0; nt < 4; ++nt) {
            int n = wn + nt * 8 + 2 * tig;
            sm_kt[n * 64 + m0]           = acc[nt][0];
            sm_kt[(n + 1) * 64 + m0]     = acc[nt][1];
            sm_kt[n * 64 + m0 + 8]       = acc[nt][2];
            sm_kt[(n + 1) * 64 + m0 + 8] = acc[nt][3];
        }
    }
    CP_WAIT(0);                                        // tile2 ready
    __syncthreads();

    // ================= pass 2: V = X Wv^T (reads SM_B) =================
    {
        float acc[4][4];
        #pragma unroll
        for (int nt = 0; nt < 4; ++nt)
            #pragma unroll
            for (int i = 0; i < 4; ++i) acc[nt][i] = 0.f;
        hmma512(smem_base, SM_B, warp, lane, acc);

        const int m0 = (warp >> 2) * 16 + gid;
        const int wn = (warp & 3) * 32;
        #pragma unroll
        for (int nt = 0; nt < 4; ++nt) {
            int n = wn + nt * 8 + 2 * tig;
            sm_v[m0 * V_STR + n]           = acc[nt][0];
            sm_v[m0 * V_STR + n + 1]       = acc[nt][1];
            sm_v[(m0 + 8) * V_STR + n]     = acc[nt][2];
            sm_v[(m0 + 8) * V_STR + n + 1] = acc[nt][3];
        }
    }
    __syncthreads();                                   // SM_B free; qt/kt/v ready

    // ---- prefetch proj weights into SM_B (overlaps whole attention) ----
    prefetch_tile(smem_base, SM_B, g_wprojT, tid);
    CP_COMMIT();                                       // g3

    // ================= Scores: S^T[h][m][t] = (Q K^T)^T * SCALE (256 thr) ==========
    if (tid < 256) {
        const int h   = tid >> 6;
        const int s6  = tid & 63;
        const int st0 = (s6 & 7) * 8;
        const int sm0 = (s6 >> 3) * 8;
        const int hd0 = h * 32;
        float* st = sm_s + h * 4096;
        u64 s2; BCAST(s2, ATT_SCALE);

        u64 acc[4][8];
        #pragma unroll
        for (int p = 0; p < 4; ++p)
            #pragma unroll
            for (int j = 0; j < 8; ++j) acc[p][j] = 0ull;

        #pragma unroll 4
        for (int d = 0; d < 32; ++d) {
            ulonglong2 q0 = *(const ulonglong2*)&sm_qt[(hd0 + d) * 64 + st0];
            ulonglong2 q1 = *(const ulonglong2*)&sm_qt[(hd0 + d) * 64 + st0 + 4];
            float4 k0v = *(const float4*)&sm_kt[(hd0 + d) * 64 + sm0];
            float4 k1v = *(const float4*)&sm_kt[(hd0 + d) * 64 + sm0 + 4];
            u64 bb[8];
            BCAST(bb[0], k0v.x); BCAST(bb[1], k0v.y); BCAST(bb[2], k0v.z); BCAST(bb[3], k0v.w);
            BCAST(bb[4], k1v.x); BCAST(bb[5], k1v.y); BCAST(bb[6], k1v.z); BCAST(bb[7], k1v.w);
            u64 ap[4] = {q0.x, q0.y, q1.x, q1.y};
            #pragma unroll
            for (int p = 0; p < 4; ++p)
                #pragma unroll
                for (int j = 0; j < 8; ++j)
                    FMA2(acc[p][j], ap[p], bb[j]);
        }
        #pragma unroll
        for (int p = 0; p < 4; ++p)
            #pragma unroll
            for (int j = 0; j < 8; ++j) {
                u64 rr; MUL2(rr, acc[p][j], s2);
                *(u64*)&st[(sm0 + j) * 64 + st0 + 2 * p] = rr;
            }
    }
    __syncthreads();

    // ================= Softmax over m per (head, token) column (256 thr) ===========
    if (tid < 256) {
        const int h = tid >> 6;
        const int t = tid & 63;
        float* col = sm_s + h * 4096 + t;
        float mx = -1e30f;
        #pragma unroll 8
        for (int m = 0; m < 64; ++m) mx = fmaxf(mx, col[m * 64]);
        float s = 0.f;
        #pragma unroll 8
        for (int m = 0; m < 64; ++m) {
            float e = __expf(col[m * 64] - mx);
            col[m * 64] = e;
            s += e;
        }
        float inv = 1.0f / s;
        #pragma unroll 8
        for (int m = 0; m < 64; ++m) col[m * 64] *= inv;
    }
    __syncthreads();

    // ================= PV: O[t][d] fp16 (proj A tile); 128 thr, 8t x 8d =========
    if (tid < 128) {
        const int pt0 = (tid & 7) * 8;
        const int d0  = (tid >> 3) * 8;
        const float* st = sm_s + (d0 >> 5) * 4096;

        u64 acc[4][8];
        #pragma unroll
        for (int p = 0; p < 4; ++p)
            #pragma unroll
            for (int j = 0; j < 8; ++j) acc[p][j] = 0ull;

        #pragma unroll 4
        for (int m = 0; m < 64; ++m) {
            ulonglong2 p0 = *(const ulonglong2*)&st[m * 64 + pt0];
            ulonglong2 p1 = *(const ulonglong2*)&st[m * 64 + pt0 + 4];
            float4 v0 = *(const float4*)&sm_v[m * V_STR + d0];
            float4 v1 = *(const float4*)&sm_v[m * V_STR + d0 + 4];
            u64 bb[8];
            BCAST(bb[0], v0.x); BCAST(bb[1], v0.y); BCAST(bb[2], v0.z); BCAST(bb[3], v0.w);
            BCAST(bb[4], v1.x); BCAST(bb[5], v1.y); BCAST(bb[6], v1.z); BCAST(bb[7], v1.w);
            u64 ap[4] = {p0.x, p0.y, p1.x, p1.y};
            #pragma unroll
            for (int p = 0; p < 4; ++p)
                #pragma unroll
                for (int j = 0; j < 8; ++j)
                    FMA2(acc[p][j], ap[p], bb[j]);
        }
        #pragma unroll
        for (int tt = 0; tt < 8; ++tt) {
            int tok = pt0 + tt;
            #pragma unroll
            for (int i = 0; i < 4; ++i) {
                F2U c0; c0.u = acc[tt >> 1][2 * i];
                F2U c1; c1.u = acc[tt >> 1][2 * i + 1];
                __half2 h2 = __floats2half2_rn(c0.f[tt & 1], c1.f[tt & 1]);
                *(u32*)&sm_a[tok * SAB + d0 + 2 * i] = *(u32*)&h2;
            }
        }
    }
    CP_WAIT(0);                                        // proj weights ready
    __syncthreads();

    // ================= Proj: HMMA 64x128x128 =================
    {
        float acc[4][4];
        #pragma unroll
        for (int nt = 0; nt < 4; ++nt)
            #pragma unroll
            for (int i = 0; i < 4; ++i) acc[nt][i] = 0.f;
        hmma512(smem_base, SM_B, warp, lane, acc);

        float* sm_final = sm_qt;                       // reuse QT region
        const int m0 = (warp >> 2) * 16 + gid;
        const int wn = (warp & 3) * 32;
        #pragma unroll
        for (int nt = 0; nt < 4; ++nt) {
            int n = wn + nt * 8 + 2 * tig;
            sm_final[n * 64 + m0]           = acc[nt][0];
            sm_final[(n + 1) * 64 + m0]     = acc[nt][1];
            sm_final[n * 64 + m0 + 8]       = acc[nt][2];
            sm_final[(n + 1) * 64 + m0 + 8] = acc[nt][3];
        }
    }
    __syncthreads();

    // ---- epilogue: coalesced channel-first store with bias ----
    {
        const float* sm_final = sm_qt;
        #pragma unroll
        for (int it = 0; it < 16; ++it) {
            int idx = it * NT + tid;
            int c = idx >> 6;
            int t = idx & 63;
            int gr = (row0 + (t >> 3)) & 255;
            int gc = (col0 + (t & 7)) & 255;
            out[(((b * 128 + c) << 8) + gr) * 256 + gc] =
                sm_final[c * 64 + t] + __ldg(&b_proj[c]);
        }
    }
}

extern "C" void kernel_launch(void* const* d_in, const int* in_sizes, int n_in,
                              void* d_out, int out_size)
{
    const float* x      = (const float*)d_in[0];
    const float* w_qkv  = (const float*)d_in[1];
    const float* w_proj = (const float*)d_in[2];
    const float* b_proj = (const float*)d_in[3];
    float* out = (float*)d_out;

    prep_weights<<<512, 128>>>(w_qkv, w_proj);

    cudaFuncSetAttribute(swin_fused_kernel,
                         cudaFuncAttributeMaxDynamicSharedMemorySize, SMEM_BYTES);
    swin_fused_kernel<<<NWIN, NT, SMEM_BYTES>>>(x, b_proj, out);
}

// round 17
// speedup vs baseline: 5.6408x; 1.6326x over previous
#include <cuda_runtime.h>
#include <cuda_fp16.h>

// SwinStyleAttention: full-HMMA pipeline. qkv+proj fp16 HMMA; scores via
// hi/lo-split fp16 HMMA (near-fp32); softmax in registers; PV via fp16 HMMA
// with hi/lo V. One CTA per 8x8 window, 512 threads, cp.async weights.
// B=8, C=128, H=W=256, WS=8, SS=4, HEADS=4, DH=32, INNER=128, L=64.

#define NWIN  8192
#define NT    512
#define ATT_SCALE 0.17677669529663687f

typedef unsigned long long u64;
typedef unsigned int u32;

// ---- SMEM byte layout (195584 B) ----
#define SM_A   0         // fp16 [64t][136]: X (qkv A); later O (proj A)
#define WB0    17408     // fp16 [128n][136] weight buf 0 (Wq, then Wv, then Wproj)
#define WB1    52224     // fp16 [128n][136] weight buf 1 (Wk); P overlays after
#define PP     52224     // fp16 P [4h*64t][72m]  (36864 B)
#define QH     89088     // fp16 Qhi [64t][136d]
#define QL     106496    // fp16 Qlo
#define KH     123904    // fp16 Khi [64m][136d]
#define KL     141312    // fp16 Klo
#define VH     158720    // fp16 VThi [128d][72m]
#define VL     177152    // fp16 VTlo
#define SMF    89088     // fp32 final [128c][64t] overlay (Q/K dead)
#define SMEM_BYTES 195584
#define SAB 136
#define PST 72

// ---- cp.async ----
#define CP16(dst, src) \
    asm volatile("cp.async.cg.shared.global [%0], [%1], 16;" :: "r"(dst), "l"(src))
#define CP_COMMIT() asm volatile("cp.async.commit_group;" ::: "memory")
#define CP_WAIT(n)  asm volatile("cp.async.wait_group %0;" :: "n"(n) : "memory")

// ---- HMMA helpers ----
__device__ __forceinline__ u32 smem_u32(const void* p) {
    u32 a;
    asm("{ .reg .u64 t; cvta.to.shared.u64 t, %1; cvt.u32.u64 %0, t; }" : "=r"(a) : "l"(p));
    return a;
}
__device__ __forceinline__ void ldsm4(u32* r, u32 addr) {
    asm volatile("ldmatrix.sync.aligned.m8n8.x4.shared.b16 {%0,%1,%2,%3}, [%4];"
        : "=r"(r[0]), "=r"(r[1]), "=r"(r[2]), "=r"(r[3]) : "r"(addr));
}
__device__ __forceinline__ void mma16816(float* c, const u32* a, u32 b0, u32 b1) {
    asm volatile("mma.sync.aligned.m16n8k16.row.col.f32.f16.f16.f32 "
        "{%0,%1,%2,%3}, {%4,%5,%6,%7}, {%8,%9}, {%0,%1,%2,%3};"
        : "+f"(c[0]), "+f"(c[1]), "+f"(c[2]), "+f"(c[3])
        : "r"(a[0]), "r"(a[1]), "r"(a[2]), "r"(a[3]), "r"(b0), "r"(b1));
}

// GEMM core (16 warps): D[64m x 128n] += A[64x128] * B^T. Warp tile 16m x 32n.
__device__ __forceinline__ void hmma512(u32 smem_base, u32 b_off, int warp, int lane,
                                        float acc[4][4]) {
    const int wm = (warp >> 2) * 16;
    const int wn = (warp & 3) * 32;
    const u32 a_base = smem_base + SM_A +
        (((wm + (lane & 15)) * SAB + ((lane >> 4) << 3)) << 1);
    const u32 b_base = smem_base + b_off +
        (((wn + (lane & 15)) * SAB + ((lane >> 4) << 3)) << 1);
    #pragma unroll
    for (int ks = 0; ks < 8; ++ks) {
        const u32 ko = (u32)(ks * 32);
        u32 a[4], bf[2][4];
        ldsm4(a,     a_base + ko);
        ldsm4(bf[0], b_base + ko);
        ldsm4(bf[1], b_base + 16 * SAB * 2 + ko);
        #pragma unroll
        for (int nt = 0; nt < 4; ++nt)
            mma16816(acc[nt], a, bf[nt >> 1][nt & 1], bf[nt >> 1][2 + (nt & 1)]);
    }
}

// hi/lo fp16 split of a pair of fp32 values -> two packed half2
__device__ __forceinline__ void cvt_hilo(float v0, float v1, u32& hi2, u32& lo2) {
    __half h0 = __float2half_rn(v0), h1 = __float2half_rn(v1);
    __half l0 = __float2half_rn(v0 - __half2float(h0));
    __half l1 = __float2half_rn(v1 - __half2float(h1));
    __half2 hh = __halves2half2(h0, h1), ll = __halves2half2(l0, l1);
    hi2 = *(u32*)&hh; lo2 = *(u32*)&ll;
}

// ---- prebuilt transposed fp16 weight images ----
__device__ __align__(16) __half g_wqkvT[384 * 128];   // [j][k]
__device__ __align__(16) __half g_wprojT[128 * 128];  // [c][d]

__global__ void prep_weights(const float* __restrict__ w_qkv, const float* __restrict__ w_proj)
{
    int r = blockIdx.x, k = threadIdx.x;
    if (r < 384) g_wqkvT[r * 128 + k] = __float2half_rn(w_qkv[k * 384 + r]);
    else         g_wprojT[(r - 384) * 128 + k] = __float2half_rn(w_proj[k * 128 + (r - 384)]);
}

__device__ __forceinline__ void prefetch_tile(u32 smem_base, u32 off, const __half* src, int tid) {
    #pragma unroll
    for (int i = 0; i < 4; ++i) {
        int idx = i * NT + tid;
        int r = idx >> 4;
        int c = (idx & 15) << 3;
        CP16(smem_base + off + (r * SAB + c) * 2, src + r * 128 + c);
    }
}

// ---- main fused kernel ----
__global__ __launch_bounds__(NT, 1)
void swin_fused_kernel(const float* __restrict__ x,
                       const float* __restrict__ b_proj,
                       float* __restrict__ out)
{
    extern __shared__ unsigned char smb[];
    __half* sm_a = (__half*)(smb + SM_A);
    const u32 smem_base = smem_u32(smb);

    const int tid  = threadIdx.x;
    const int warp = tid >> 5;
    const int lane = tid & 31;
    const int gid  = lane >> 2;
    const int tig  = lane & 3;

    const int win = blockIdx.x;
    const int b   = win >> 10;
    const int wh  = (win >> 5) & 31;
    const int ww  = win & 31;
    const int row0 = wh * 8 + 4;
    const int col0 = ww * 8 + 4;

    // ---- prefetch Wq ----
    prefetch_tile(smem_base, WB0, g_wqkvT, tid);
    CP_COMMIT();                                       // g0

    // ---- gather X -> sm_a[t][c] fp16 ----
    #pragma unroll
    for (int it = 0; it < 16; ++it) {
        int idx = it * NT + tid;         // ch*64 + t
        int ch  = idx >> 6;
        int t   = idx & 63;
        int gr  = (row0 + (t >> 3)) & 255;
        int gc  = (col0 + (t & 7)) & 255;
        sm_a[t * SAB + ch] = __float2half_rn(x[(((b * 128 + ch) << 8) + gr) * 256 + gc]);
    }

    prefetch_tile(smem_base, WB1, g_wqkvT + 128 * 128, tid);
    CP_COMMIT();                                       // g1
    CP_WAIT(1);
    __syncthreads();

    const int m0 = (warp >> 2) * 16 + gid;
    const int wn = (warp & 3) * 32;

    // ================= pass 0: Q -> Qhi/Qlo [t][d] =================
    {
        float acc[4][4];
        #pragma unroll
        for (int nt = 0; nt < 4; ++nt)
            #pragma unroll
            for (int i = 0; i < 4; ++i) acc[nt][i] = 0.f;
        hmma512(smem_base, WB0, warp, lane, acc);
        #pragma unroll
        for (int nt = 0; nt < 4; ++nt) {
            int n = wn + nt * 8 + 2 * tig;
            u32 h2, l2;
            cvt_hilo(acc[nt][0], acc[nt][1], h2, l2);
            *(u32*)(smb + QH + (m0 * SAB + n) * 2) = h2;
            *(u32*)(smb + QL + (m0 * SAB + n) * 2) = l2;
            cvt_hilo(acc[nt][2], acc[nt][3], h2, l2);
            *(u32*)(smb + QH + ((m0 + 8) * SAB + n) * 2) = h2;
            *(u32*)(smb + QL + ((m0 + 8) * SAB + n) * 2) = l2;
        }
    }
    __syncthreads();                                   // WB0 free

    prefetch_tile(smem_base, WB0, g_wqkvT + 2 * 128 * 128, tid);
    CP_COMMIT();                                       // g2
    CP_WAIT(1);                                        // g1 done
    __syncthreads();

    // ================= pass 1: K -> Khi/Klo [m][d] =================
    {
        float acc[4][4];
        #pragma unroll
        for (int nt = 0; nt < 4; ++nt)
            #pragma unroll
            for (int i = 0; i < 4; ++i) acc[nt][i] = 0.f;
        hmma512(smem_base, WB1, warp, lane, acc);
        #pragma unroll
        for (int nt = 0; nt < 4; ++nt) {
            int n = wn + nt * 8 + 2 * tig;
            u32 h2, l2;
            cvt_hilo(acc[nt][0], acc[nt][1], h2, l2);
            *(u32*)(smb + KH + (m0 * SAB + n) * 2) = h2;
            *(u32*)(smb + KL + (m0 * SAB + n) * 2) = l2;
            cvt_hilo(acc[nt][2], acc[nt][3], h2, l2);
            *(u32*)(smb + KH + ((m0 + 8) * SAB + n) * 2) = h2;
            *(u32*)(smb + KL + ((m0 + 8) * SAB + n) * 2) = l2;
        }
    }
    CP_WAIT(0);                                        // g2 done
    __syncthreads();

    // ================= pass 2: V -> VThi/VTlo [d][m] =================
    {
        float acc[4][4];
        #pragma unroll
        for (int nt = 0; nt < 4; ++nt)
            #pragma unroll
            for (int i = 0; i < 4; ++i) acc[nt][i] = 0.f;
        hmma512(smem_base, WB0, warp, lane, acc);
        #pragma unroll
        for (int nt = 0; nt < 4; ++nt) {
            int n = wn + nt * 8 + 2 * tig;             // d
            #pragma unroll
            for (int i = 0; i < 4; ++i) {
                int d = n + (i & 1);
                int m = m0 + ((i >> 1) << 3);
                float v = acc[nt][i];
                __half hv = __float2half_rn(v);
                __half lv = __float2half_rn(v - __half2float(hv));
                *(__half*)(smb + VH + (d * PST + m) * 2) = hv;
                *(__half*)(smb + VL + (d * PST + m) * 2) = lv;
            }
        }
    }
    __syncthreads();                                   // WB0 free; Q/K/V ready

    prefetch_tile(smem_base, WB0, g_wprojT, tid);      // proj weights
    CP_COMMIT();                                       // g3

    // ================= Scores + softmax (in regs) + P fp16 =================
    // warp tile: head h = warp>>2, tokens t0..t0+15; full 64 m per warp.
    {
        const int h   = warp >> 2;
        const int t0  = (warp & 3) * 16;
        const int hd0 = h * 32;
        const u32 lro = (u32)(((lane & 15) * SAB + hd0 + ((lane >> 4) << 3)) << 1);
        const u32 a_hi = smem_base + QH + (u32)((t0 * SAB) << 1) + lro;
        const u32 a_lo = smem_base + QL + (u32)((t0 * SAB) << 1) + lro;
        const u32 b_hi = smem_base + KH + lro;
        const u32 b_lo = smem_base + KL + lro;

        float acc[8][4];
        #pragma unroll
        for (int nt = 0; nt < 8; ++nt)
            #pragma unroll
            for (int i = 0; i < 4; ++i) acc[nt][i] = 0.f;

        #pragma unroll
        for (int ks = 0; ks < 2; ++ks) {
            const u32 ko = (u32)(ks * 32);
            u32 ah[4], al[4];
            ldsm4(ah, a_hi + ko);
            ldsm4(al, a_lo + ko);
            #pragma unroll
            for (int mg = 0; mg < 4; ++mg) {
                u32 bh[4], bl[4];
                ldsm4(bh, b_hi + mg * 16 * SAB * 2 + ko);
                ldsm4(bl, b_lo + mg * 16 * SAB * 2 + ko);
                #pragma unroll
                for (int ni = 0; ni < 2; ++ni) {
                    int nt = mg * 2 + ni;
                    mma16816(acc[nt], ah, bh[ni], bh[2 + ni]);
                    mma16816(acc[nt], ah, bl[ni], bl[2 + ni]);
                    mma16816(acc[nt], al, bh[ni], bh[2 + ni]);
                }
            }
        }

        // scale, then register softmax over rows (gid) and (gid+8)
        float mx0 = -1e30f, mx1 = -1e30f;
        #pragma unroll
        for (int nt = 0; nt < 8; ++nt) {
            #pragma unroll
            for (int i = 0; i < 4; ++i) acc[nt][i] *= ATT_SCALE;
            mx0 = fmaxf(mx0, fmaxf(acc[nt][0], acc[nt][1]));
            mx1 = fmaxf(mx1, fmaxf(acc[nt][2], acc[nt][3]));
        }
        mx0 = fmaxf(mx0, __shfl_xor_sync(0xffffffffu, mx0, 1));
        mx0 = fmaxf(mx0, __shfl_xor_sync(0xffffffffu, mx0, 2));
        mx1 = fmaxf(mx1, __shfl_xor_sync(0xffffffffu, mx1, 1));
        mx1 = fmaxf(mx1, __shfl_xor_sync(0xffffffffu, mx1, 2));
        float s0 = 0.f, s1 = 0.f;
        #pragma unroll
        for (int nt = 0; nt < 8; ++nt) {
            acc[nt][0] = __expf(acc[nt][0] - mx0);
            acc[nt][1] = __expf(acc[nt][1] - mx0);
            acc[nt][2] = __expf(acc[nt][2] - mx1);
            acc[nt][3] = __expf(acc[nt][3] - mx1);
            s0 += acc[nt][0] + acc[nt][1];
            s1 += acc[nt][2] + acc[nt][3];
        }
        s0 += __shfl_xor_sync(0xffffffffu, s0, 1);
        s0 += __shfl_xor_sync(0xffffffffu, s0, 2);
        s1 += __shfl_xor_sync(0xffffffffu, s1, 1);
        s1 += __shfl_xor_sync(0xffffffffu, s1, 2);
        float inv0 = 1.0f / s0, inv1 = 1.0f / s1;

        const int prow = h * 64 + t0;
        #pragma unroll
        for (int nt = 0; nt < 8; ++nt) {
            int mcol = nt * 8 + 2 * tig;
            __half2 p01 = __floats2half2_rn(acc[nt][0] * inv0, acc[nt][1] * inv0);
            __half2 p23 = __floats2half2_rn(acc[nt][2] * inv1, acc[nt][3] * inv1);
            *(u32*)(smb + PP + ((prow + gid) * PST + mcol) * 2) = *(u32*)&p01;
            *(u32*)(smb + PP + ((prow + gid + 8) * PST + mcol) * 2) = *(u32*)&p23;
        }
    }
    __syncthreads();

    // ================= PV: O[t][d] = P Vhi^T + P Vlo^T -> fp16 into SM_A ==========
    {
        const int h   = warp >> 2;
        const int t0  = (warp & 3) * 16;
        const int hd0 = h * 32;
        const u32 a_p  = smem_base + PP +
            (u32)((((h * 64 + t0 + (lane & 15)) * PST + ((lane >> 4) << 3))) << 1);
        const u32 b_ro = (u32)((((hd0 + (lane & 15)) * PST + ((lane >> 4) << 3))) << 1);
        const u32 b_hi = smem_base + VH + b_ro;
        const u32 b_lo = smem_base + VL + b_ro;

        float acc[4][4];
        #pragma unroll
        for (int nt = 0; nt < 4; ++nt)
            #pragma unroll
            for (int i = 0; i < 4; ++i) acc[nt][i] = 0.f;

        #pragma unroll
        for (int ks = 0; ks < 4; ++ks) {
            const u32 ko = (u32)(ks * 32);
            u32 ap[4];
            ldsm4(ap, a_p + ko);
            #pragma unroll
            for (int dg = 0; dg < 2; ++dg) {
                u32 bh[4], bl[4];
                ldsm4(bh, b_hi + dg * 16 * PST * 2 + ko);
                ldsm4(bl, b_lo + dg * 16 * PST * 2 + ko);
                #pragma unroll
                for (int ni = 0; ni < 2; ++ni) {
                    int nt = dg * 2 + ni;
                    mma16816(acc[nt], ap, bh[ni], bh[2 + ni]);
                    mma16816(acc[nt], ap, bl[ni], bl[2 + ni]);
                }
            }
        }
        #pragma unroll
        for (int nt = 0; nt < 4; ++nt) {
            int d = hd0 + nt * 8 + 2 * tig;
            __half2 o01 = __floats2half2_rn(acc[nt][0], acc[nt][1]);
            __half2 o23 = __floats2half2_rn(acc[nt][2], acc[nt][3]);
            *(u32*)(smb + SM_A + ((t0 + gid) * SAB + d) * 2) = *(u32*)&o01;
            *(u32*)(smb + SM_A + ((t0 + gid + 8) * SAB + d) * 2) = *(u32*)&o23;
        }
    }
    CP_WAIT(0);                                        // proj weights ready
    __syncthreads();

    // ================= Proj: HMMA 64x128x128 -> SMF[c][t] =================
    {
        float acc[4][4];
        #pragma unroll
        for (int nt = 0; nt < 4; ++nt)
            #pragma unroll
            for (int i = 0; i < 4; ++i) acc[nt][i] = 0.f;
        hmma512(smem_base, WB0, warp, lane, acc);

        float* sm_final = (float*)(smb + SMF);
        #pragma unroll
        for (int nt = 0; nt < 4; ++nt) {
            int n = wn + nt * 8 + 2 * tig;
            sm_final[n * 64 + m0]           = acc[nt][0];
            sm_final[(n + 1) * 64 + m0]     = acc[nt][1];
            sm_final[n * 64 + m0 + 8]       = acc[nt][2];
            sm_final[(n + 1) * 64 + m0 + 8] = acc[nt][3];
        }
    }
    __syncthreads();

    // ---- epilogue: coalesced channel-first store with bias ----
    {
        const float* sm_final = (const float*)(smb + SMF);
        #pragma unroll
        for (int it = 0; it < 16; ++it) {
            int idx = it * NT + tid;
            int c = idx >> 6;
            int t = idx & 63;
            int gr = (row0 + (t >> 3)) & 255;
            int gc = (col0 + (t & 7)) & 255;
            out[(((b * 128 + c) << 8) + gr) * 256 + gc] =
                sm_final[c * 64 + t] + __ldg(&b_proj[c]);
        }
    }
}

extern "C" void kernel_launch(void* const* d_in, const int* in_sizes, int n_in,
                              void* d_out, int out_size)
{
    const float* x      = (const float*)d_in[0];
    const float* w_qkv  = (const float*)d_in[1];
    const float* w_proj = (const float*)d_in[2];
    const float* b_proj = (const float*)d_in[3];
    float* out = (float*)d_out;

    prep_weights<<<512, 128>>>(w_qkv, w_proj);

    cudaFuncSetAttribute(swin_fused_kernel,
                         cudaFuncAttributeMaxDynamicSharedMemorySize, SMEM_BYTES);
    swin_fused_kernel<<<NWIN, NT, SMEM_BYTES>>>(x, b_proj, out);
}